// round 6
// baseline (speedup 1.0000x reference)
#include <cuda_runtime.h>

#define BB   8
#define TT   2000
#define DD   64
#define NRES 2000
#define KPAD 2048
#define KQ   (KPAD/4)     // 512 float4 per row
#define MAXC 16           // column slots per block (padded)

// ---------------- device scratch ---------------------------------------------
__device__ float    g_WresT[NRES * KPAD];        // [n][k], k zero-padded (16 MB)
__device__ float    g_U[TT * BB * NRES];         // [t][b][n]              (128 MB)
__device__ float    g_H[BB * TT * NRES];         // [b][t][n], pre-augmented
__device__ float    g_S[2 * BB * NRES];          // double-buffered state
__device__ unsigned g_barCnt = 0;
__device__ unsigned g_barGen = 0;

// ---------------- software grid barrier (proven atomic version) --------------
__device__ __forceinline__ void grid_sync(unsigned nblk) {
    __threadfence();
    __syncthreads();
    if (threadIdx.x == 0) {
        volatile unsigned* genp = &g_barGen;
        unsigned gen = *genp;
        if (atomicInc(&g_barCnt, nblk - 1) == nblk - 1) {
            *genp = gen + 1;
        } else {
            while (*genp == gen) { __nanosleep(64); }
        }
    }
    __syncthreads();
}

// ---------------- Wres -> WresT (padded) -------------------------------------
__global__ void k_transpose(const float* __restrict__ Wres) {
    __shared__ float tile[32][33];
    int tx = threadIdx.x, ty = threadIdx.y;
    int k0 = blockIdx.x * 32;           // k tile (0..2047)
    int n0 = blockIdx.y * 32;           // n tile (0..1999)
    int k = k0 + ty, n = n0 + tx;
    float v = 0.f;
    if (k < NRES && n < NRES) v = Wres[k * NRES + n];
    tile[ty][tx] = v;
    __syncthreads();
    int nn = n0 + ty, kk = k0 + tx;
    if (nn < NRES) g_WresT[nn * KPAD + kk] = tile[tx][ty];
}

// ---------------- U[t][b][n] = sum_d x[b][t][d] * Win[d][n] ------------------
__global__ void k_u(const float* __restrict__ x, const float* __restrict__ Win) {
    __shared__ float xs[BB][DD];
    int t = blockIdx.x, tid = threadIdx.x;
    if (tid < BB * (DD / 4)) {
        int b = tid / (DD / 4), q = tid % (DD / 4);
        ((float4*)&xs[b][0])[q] = ((const float4*)(x + (size_t)(b * TT + t) * DD))[q];
    }
    __syncthreads();
    for (int n = tid; n < NRES; n += blockDim.x) {
        float acc[BB];
        #pragma unroll
        for (int b = 0; b < BB; b++) acc[b] = 0.f;
        #pragma unroll
        for (int d4 = 0; d4 < DD / 4; d4++) {
            float w0 = Win[(d4 * 4 + 0) * NRES + n];
            float w1 = Win[(d4 * 4 + 1) * NRES + n];
            float w2 = Win[(d4 * 4 + 2) * NRES + n];
            float w3 = Win[(d4 * 4 + 3) * NRES + n];
            #pragma unroll
            for (int b = 0; b < BB; b++) {
                float4 xv = *(const float4*)&xs[b][d4 * 4];
                acc[b] = fmaf(xv.x, w0, acc[b]);
                acc[b] = fmaf(xv.y, w1, acc[b]);
                acc[b] = fmaf(xv.z, w2, acc[b]);
                acc[b] = fmaf(xv.w, w3, acc[b]);
            }
        }
        #pragma unroll
        for (int b = 0; b < BB; b++) g_U[(size_t)(t * BB + b) * NRES + n] = acc[b];
    }
}

// ---------------- persistent recurrence kernel -------------------------------
// R1 skeleton; only the GEMM work mapping changed:
// thread tid: out = tid&127 -> (b = out&7, c = out>>3), K-half = tid>>7.
// Each thread accumulates its (c,b) output over 1024 k in 4 scalar chains.
// Reduction: K-half-1 threads store to p_sh; K-half-0 threads add + finalize.
// Zero shuffles.
__global__ void __launch_bounds__(256, 1) k_esn() {
    extern __shared__ float smem[];
    float* s_sh = smem;                 // BB * KPAD
    float* w_sh = smem + BB * KPAD;     // MAXC * KPAD
    __shared__ float p_sh[MAXC][BB];

    const int tid  = threadIdx.x;
    const int nblk = gridDim.x;
    const int bid  = blockIdx.x;

    const int base = NRES / nblk, rem = NRES % nblk;
    const int c0    = bid * base + (bid < rem ? bid : rem);
    const int ncols = base + (bid < rem ? 1 : 0);   // <= 16

    // preload this block's WresT slice into smem (once; pad unused slots w/ 0)
    {
        float4*       w4  = (float4*)w_sh;
        const float4* gW4 = (const float4*)g_WresT;
        for (int i = tid; i < MAXC * KQ; i += blockDim.x) {
            int c = i >> 9;
            int q = i & (KQ - 1);
            float4 v = make_float4(0.f, 0.f, 0.f, 0.f);
            if (c < ncols) v = gW4[(size_t)(c0 + c) * KQ + q];
            w4[i] = v;
        }
    }

    // zero state buffer 0 (grid-strided)
    for (int i = bid * blockDim.x + tid; i < BB * NRES; i += nblk * blockDim.x)
        g_S[i] = 0.f;

    grid_sync(nblk);

    const int out = tid & 127;
    const int kh  = tid >> 7;           // K-half 0/1
    const int ob  = out & 7;            // batch row
    const int oc  = out >> 3;           // column slot 0..15

    const float4* wp = (const float4*)w_sh + (size_t)oc * KQ + kh * 256;
    const float4* sp = (const float4*)s_sh + (size_t)ob * KQ + kh * 256;

    const bool f_act = (kh == 0) && (oc < ncols);
    const int  f_col = c0 + oc;

    #pragma unroll 1
    for (int t = 0; t < TT; t++) {
        const int buf = t & 1;

        // prefetch this step's input-projection value (DRAM latency hidden
        // behind staging)
        float uval = 0.f;
        if (f_act) uval = __ldg(&g_U[(size_t)(t * BB + ob) * NRES + f_col]);

        // stage S (L2) -> smem, zero-padded to 2048
        {
            const float* Sp = g_S + (size_t)buf * (BB * NRES);
            float4* s4 = (float4*)s_sh;
            for (int i = tid; i < BB * KQ; i += blockDim.x) {
                int b = i >> 9;
                int q = i & (KQ - 1);
                float4 v = make_float4(0.f, 0.f, 0.f, 0.f);
                if (q * 4 < NRES)
                    v = __ldcg((const float4*)(Sp + (size_t)b * NRES + q * 4));
                s4[(size_t)b * KQ + q] = v;
            }
        }
        __syncthreads();

        // ---- GEMM: one (col,b) output per thread over 1024 k, 4 FMA chains
        float ax = 0.f, ay = 0.f, az = 0.f, aw = 0.f;
        #pragma unroll 4
        for (int q = 0; q < 256; q++) {
            const float4 w = wp[q];
            const float4 s = sp[q];
            ax = fmaf(s.x, w.x, ax);
            ay = fmaf(s.y, w.y, ay);
            az = fmaf(s.z, w.z, az);
            aw = fmaf(s.w, w.w, aw);
        }
        const float part = (ax + ay) + (az + aw);

        if (kh == 1) p_sh[oc][ob] = part;
        __syncthreads();

        // ---- finalize (K-half-0 threads own the outputs) ----
        if (f_act) {
            float v = part + p_sh[oc][ob] + uval;
            float h = tanhf(v);
            const int nbuf = buf ^ 1;
            __stcg(&g_S[(size_t)nbuf * (BB * NRES) + (size_t)ob * NRES + f_col], h);
            float ha = ((f_col & 1) == 0) ? h * h : h;   // pre-augment for k_out
            g_H[((size_t)ob * TT + t) * NRES + f_col] = ha;
        }

        grid_sync(nblk);
    }
}

// ---------------- readout: out[b][t][d] = Haug[b][t][:] @ Wout ---------------
#define OT   8
#define HSTR 2004
__global__ void __launch_bounds__(256, 2) k_out(const float* __restrict__ Wout,
                                                float* __restrict__ out) {
    extern __shared__ float hs[];            // [OT][HSTR]
    __shared__ float ps[4][64][OT];
    const int tid = threadIdx.x;
    const int b   = blockIdx.y;
    const int t0  = blockIdx.x * OT;

    for (int r = 0; r < OT; r++) {
        const float4* src = (const float4*)(g_H + ((size_t)b * TT + (t0 + r)) * NRES);
        float4*       dst = (float4*)(hs + r * HSTR);
        for (int i = tid; i < 500; i += 256) dst[i] = __ldcg(src + i);
    }
    __syncthreads();

    const int d  = tid & 63;
    const int nq = tid >> 6;                 // 0..3
    float acc[OT];
    #pragma unroll
    for (int r = 0; r < OT; r++) acc[r] = 0.f;

    for (int q = nq; q < 500; q += 4) {
        const int n = q * 4;
        const float w0 = __ldg(&Wout[(size_t)(n + 0) * DD + d]);
        const float w1 = __ldg(&Wout[(size_t)(n + 1) * DD + d]);
        const float w2 = __ldg(&Wout[(size_t)(n + 2) * DD + d]);
        const float w3 = __ldg(&Wout[(size_t)(n + 3) * DD + d]);
        #pragma unroll
        for (int r = 0; r < OT; r++) {
            const float4 h4 = *(const float4*)(hs + r * HSTR + n);
            acc[r] = fmaf(h4.x, w0, acc[r]);
            acc[r] = fmaf(h4.y, w1, acc[r]);
            acc[r] = fmaf(h4.z, w2, acc[r]);
            acc[r] = fmaf(h4.w, w3, acc[r]);
        }
    }
    #pragma unroll
    for (int r = 0; r < OT; r++) ps[nq][d][r] = acc[r];
    __syncthreads();

    for (int i = tid; i < 64 * OT; i += 256) {
        int dd = i >> 3, rr = i & (OT - 1);
        float v = ps[0][dd][rr] + ps[1][dd][rr] + ps[2][dd][rr] + ps[3][dd][rr];
        out[((size_t)b * TT + (t0 + rr)) * DD + dd] = v;
    }
}

// ---------------- launch ------------------------------------------------------
extern "C" void kernel_launch(void* const* d_in, const int* in_sizes, int n_in,
                              void* d_out, int out_size) {
    const float* x    = (const float*)d_in[0];
    const float* Win  = (const float*)d_in[1];
    const float* Wres = (const float*)d_in[2];
    const float* Wout = (const float*)d_in[3];
    float*       out  = (float*)d_out;

    int dev = 0;
    cudaGetDevice(&dev);
    int nsm = 148;
    cudaDeviceGetAttribute(&nsm, cudaDevAttrMultiProcessorCount, dev);
    int nblk = nsm < 148 ? nsm : 148;   // 1 block/SM, all resident
    if (nblk < 125) nblk = 125;         // 16-slot capacity guard

    const size_t smem_main = (size_t)(BB * KPAD + MAXC * KPAD) * sizeof(float); // 192 KB
    cudaFuncSetAttribute(k_esn, cudaFuncAttributeMaxDynamicSharedMemorySize, (int)smem_main);
    const size_t smem_out = (size_t)OT * HSTR * sizeof(float);                  // ~64 KB
    cudaFuncSetAttribute(k_out, cudaFuncAttributeMaxDynamicSharedMemorySize, (int)smem_out);

    k_transpose<<<dim3(KPAD / 32, (NRES + 31) / 32), dim3(32, 32)>>>(Wres);
    k_u<<<TT, 256>>>(x, Win);
    k_esn<<<nblk, 256, smem_main>>>();
    k_out<<<dim3(TT / OT, BB), 256, smem_out>>>(Wout, out);
}

// round 7
// speedup vs baseline: 4.0260x; 4.0260x over previous
#include <cuda_runtime.h>

#define BB   8
#define TT   2000
#define DD   64
#define NRES 2000
#define KPAD 2048
#define KQ   (KPAD/4)     // 512 float4 of real data per row
#define SQ   513          // smem row stride in float4 (2052 floats) -> conflict-free
#define MAXC 16           // column slots per block (padded)

// ---------------- device scratch ---------------------------------------------
__device__ float    g_WresT[NRES * KPAD];        // [n][k], k zero-padded (16 MB)
__device__ float    g_U[TT * BB * NRES];         // [t][b][n]              (128 MB)
__device__ float    g_H[BB * TT * NRES];         // [b][t][n], pre-augmented
__device__ float    g_S[2 * BB * NRES];          // double-buffered state
__device__ unsigned g_barCnt = 0;
__device__ unsigned g_barGen = 0;

// ---------------- software grid barrier (proven atomic version) --------------
__device__ __forceinline__ void grid_sync(unsigned nblk) {
    __threadfence();
    __syncthreads();
    if (threadIdx.x == 0) {
        volatile unsigned* genp = &g_barGen;
        unsigned gen = *genp;
        if (atomicInc(&g_barCnt, nblk - 1) == nblk - 1) {
            *genp = gen + 1;
        } else {
            while (*genp == gen) { __nanosleep(64); }
        }
    }
    __syncthreads();
}

// ---------------- Wres -> WresT (padded) -------------------------------------
__global__ void k_transpose(const float* __restrict__ Wres) {
    __shared__ float tile[32][33];
    int tx = threadIdx.x, ty = threadIdx.y;
    int k0 = blockIdx.x * 32;           // k tile (0..2047)
    int n0 = blockIdx.y * 32;           // n tile (0..1999)
    int k = k0 + ty, n = n0 + tx;
    float v = 0.f;
    if (k < NRES && n < NRES) v = Wres[k * NRES + n];
    tile[ty][tx] = v;
    __syncthreads();
    int nn = n0 + ty, kk = k0 + tx;
    if (nn < NRES) g_WresT[nn * KPAD + kk] = tile[tx][ty];
}

// ---------------- U[t][b][n] = sum_d x[b][t][d] * Win[d][n] ------------------
__global__ void k_u(const float* __restrict__ x, const float* __restrict__ Win) {
    __shared__ float xs[BB][DD];
    int t = blockIdx.x, tid = threadIdx.x;
    if (tid < BB * (DD / 4)) {
        int b = tid / (DD / 4), q = tid % (DD / 4);
        ((float4*)&xs[b][0])[q] = ((const float4*)(x + (size_t)(b * TT + t) * DD))[q];
    }
    __syncthreads();
    for (int n = tid; n < NRES; n += blockDim.x) {
        float acc[BB];
        #pragma unroll
        for (int b = 0; b < BB; b++) acc[b] = 0.f;
        #pragma unroll
        for (int d4 = 0; d4 < DD / 4; d4++) {
            float w0 = Win[(d4 * 4 + 0) * NRES + n];
            float w1 = Win[(d4 * 4 + 1) * NRES + n];
            float w2 = Win[(d4 * 4 + 2) * NRES + n];
            float w3 = Win[(d4 * 4 + 3) * NRES + n];
            #pragma unroll
            for (int b = 0; b < BB; b++) {
                float4 xv = *(const float4*)&xs[b][d4 * 4];
                acc[b] = fmaf(xv.x, w0, acc[b]);
                acc[b] = fmaf(xv.y, w1, acc[b]);
                acc[b] = fmaf(xv.z, w2, acc[b]);
                acc[b] = fmaf(xv.w, w3, acc[b]);
            }
        }
        #pragma unroll
        for (int b = 0; b < BB; b++) g_U[(size_t)(t * BB + b) * NRES + n] = acc[b];
    }
}

// ---------------- persistent recurrence kernel -------------------------------
// thread: out = tid&127 -> (b = out&7, c = out>>3); K-half = tid>>7.
// One (col,b) output per thread over 1024 k, 4 scalar FMA chains; reduction is
// one p_sh store + one add (zero shuffles). Smem rows strided SQ=513 float4:
// row r starts at f4-group (r % 8) -> warp's 4 w-rows / 8 s-rows hit distinct
// 4-bank groups every iteration: conflict-free.
__global__ void __launch_bounds__(256, 1) k_esn() {
    extern __shared__ float smem[];
    float* s_sh = smem;                      // BB  * 4*SQ floats
    float* w_sh = smem + BB * 4 * SQ;        // MAXC* 4*SQ floats
    __shared__ float p_sh[MAXC][BB];

    const int tid  = threadIdx.x;
    const int nblk = gridDim.x;
    const int bid  = blockIdx.x;

    const int base = NRES / nblk, rem = NRES % nblk;
    const int c0    = bid * base + (bid < rem ? bid : rem);
    const int ncols = base + (bid < rem ? 1 : 0);   // <= 16

    // preload this block's WresT slice into smem (once; unused slots zeroed)
    {
        float4*       w4  = (float4*)w_sh;
        const float4* gW4 = (const float4*)g_WresT;
        for (int i = tid; i < MAXC * KQ; i += 256) {
            int c = i >> 9;                  // / 512
            int q = i & (KQ - 1);
            float4 v = make_float4(0.f, 0.f, 0.f, 0.f);
            if (c < ncols) v = gW4[(size_t)(c0 + c) * KQ + q];
            w4[(size_t)c * SQ + q] = v;
        }
    }

    // zero state buffer 0 (grid-strided)
    for (int i = bid * 256 + tid; i < BB * NRES; i += nblk * 256)
        g_S[i] = 0.f;

    grid_sync(nblk);

    const int out = tid & 127;
    const int kh  = tid >> 7;           // K-half 0/1
    const int ob  = out & 7;            // batch row
    const int oc  = out >> 3;           // column slot 0..15

    const float4* wp = (const float4*)w_sh + (size_t)oc * SQ + kh * 256;
    const float4* sp = (const float4*)s_sh + (size_t)ob * SQ + kh * 256;

    const bool f_act = (kh == 0) && (oc < ncols);
    const int  f_col = c0 + oc;

    #pragma unroll 1
    for (int t = 0; t < TT; t++) {
        const int buf = t & 1;

        // prefetch this step's input-projection value
        float uval = 0.f;
        if (f_act) uval = __ldg(&g_U[(size_t)(t * BB + ob) * NRES + f_col]);

        // stage S (L2) -> smem, zero-padded to 2048
        {
            const float* Sp = g_S + (size_t)buf * (BB * NRES);
            float4* s4 = (float4*)s_sh;
            for (int i = tid; i < BB * KQ; i += 256) {
                int b = i >> 9;
                int q = i & (KQ - 1);
                float4 v = make_float4(0.f, 0.f, 0.f, 0.f);
                if (q < 500)
                    v = __ldcg((const float4*)(Sp + (size_t)b * NRES + q * 4));
                s4[(size_t)b * SQ + q] = v;
            }
        }
        __syncthreads();

        // ---- GEMM: one (col,b) output per thread over 1024 k, 4 FMA chains
        float ax = 0.f, ay = 0.f, az = 0.f, aw = 0.f;
        #pragma unroll 8
        for (int q = 0; q < 256; q++) {
            const float4 w = wp[q];
            const float4 s = sp[q];
            ax = fmaf(s.x, w.x, ax);
            ay = fmaf(s.y, w.y, ay);
            az = fmaf(s.z, w.z, az);
            aw = fmaf(s.w, w.w, aw);
        }
        const float part = (ax + ay) + (az + aw);

        if (kh == 1) p_sh[oc][ob] = part;
        __syncthreads();

        // ---- finalize (K-half-0 threads own the outputs) ----
        if (f_act) {
            float v = part + p_sh[oc][ob] + uval;
            float h = tanhf(v);
            const int nbuf = buf ^ 1;
            __stcg(&g_S[(size_t)nbuf * (BB * NRES) + (size_t)ob * NRES + f_col], h);
            float ha = ((f_col & 1) == 0) ? h * h : h;   // pre-augment for k_out
            g_H[((size_t)ob * TT + t) * NRES + f_col] = ha;
        }

        grid_sync(nblk);
    }
}

// ---------------- readout: out[b][t][d] = Haug[b][t][:] @ Wout ---------------
#define OT   8
#define HSTR 2004
__global__ void __launch_bounds__(256, 2) k_out(const float* __restrict__ Wout,
                                                float* __restrict__ out) {
    extern __shared__ float hs[];            // [OT][HSTR]
    __shared__ float ps[4][64][OT];
    const int tid = threadIdx.x;
    const int b   = blockIdx.y;
    const int t0  = blockIdx.x * OT;

    for (int r = 0; r < OT; r++) {
        const float4* src = (const float4*)(g_H + ((size_t)b * TT + (t0 + r)) * NRES);
        float4*       dst = (float4*)(hs + r * HSTR);
        for (int i = tid; i < 500; i += 256) dst[i] = __ldcg(src + i);
    }
    __syncthreads();

    const int d  = tid & 63;
    const int nq = tid >> 6;                 // 0..3
    float acc[OT];
    #pragma unroll
    for (int r = 0; r < OT; r++) acc[r] = 0.f;

    for (int q = nq; q < 500; q += 4) {
        const int n = q * 4;
        const float w0 = __ldg(&Wout[(size_t)(n + 0) * DD + d]);
        const float w1 = __ldg(&Wout[(size_t)(n + 1) * DD + d]);
        const float w2 = __ldg(&Wout[(size_t)(n + 2) * DD + d]);
        const float w3 = __ldg(&Wout[(size_t)(n + 3) * DD + d]);
        #pragma unroll
        for (int r = 0; r < OT; r++) {
            const float4 h4 = *(const float4*)(hs + r * HSTR + n);
            acc[r] = fmaf(h4.x, w0, acc[r]);
            acc[r] = fmaf(h4.y, w1, acc[r]);
            acc[r] = fmaf(h4.z, w2, acc[r]);
            acc[r] = fmaf(h4.w, w3, acc[r]);
        }
    }
    #pragma unroll
    for (int r = 0; r < OT; r++) ps[nq][d][r] = acc[r];
    __syncthreads();

    for (int i = tid; i < 64 * OT; i += 256) {
        int dd = i >> 3, rr = i & (OT - 1);
        float v = ps[0][dd][rr] + ps[1][dd][rr] + ps[2][dd][rr] + ps[3][dd][rr];
        out[((size_t)b * TT + (t0 + rr)) * DD + dd] = v;
    }
}

// ---------------- launch ------------------------------------------------------
extern "C" void kernel_launch(void* const* d_in, const int* in_sizes, int n_in,
                              void* d_out, int out_size) {
    const float* x    = (const float*)d_in[0];
    const float* Win  = (const float*)d_in[1];
    const float* Wres = (const float*)d_in[2];
    const float* Wout = (const float*)d_in[3];
    float*       out  = (float*)d_out;

    int dev = 0;
    cudaGetDevice(&dev);
    int nsm = 148;
    cudaDeviceGetAttribute(&nsm, cudaDevAttrMultiProcessorCount, dev);
    int nblk = nsm < 148 ? nsm : 148;   // 1 block/SM, all resident
    if (nblk < 125) nblk = 125;         // 16-slot capacity guard

    const size_t smem_main = (size_t)(BB + MAXC) * 4 * SQ * sizeof(float);  // ~197 KB
    cudaFuncSetAttribute(k_esn, cudaFuncAttributeMaxDynamicSharedMemorySize, (int)smem_main);
    const size_t smem_out = (size_t)OT * HSTR * sizeof(float);              // ~64 KB
    cudaFuncSetAttribute(k_out, cudaFuncAttributeMaxDynamicSharedMemorySize, (int)smem_out);

    k_transpose<<<dim3(KPAD / 32, (NRES + 31) / 32), dim3(32, 32)>>>(Wres);
    k_u<<<TT, 256>>>(x, Win);
    k_esn<<<nblk, 256, smem_main>>>();
    k_out<<<dim3(TT / OT, BB), 256, smem_out>>>(Wout, out);
}

// round 8
// speedup vs baseline: 6.7625x; 1.6797x over previous
#include <cuda_runtime.h>

#define BB   8
#define TT   2000
#define DD   64
#define NRES 2000
#define KPAD 2048
#define KQ   (KPAD/4)     // 512 float4 per row
#define MAXC 16           // max column slots per block

// ---------------- device scratch ---------------------------------------------
__device__ float    g_WresT[NRES * KPAD];        // [n][k], k zero-padded (16 MB)
__device__ float    g_U[TT * BB * NRES];         // [t][b][n]              (128 MB)
__device__ float    g_H[BB * TT * NRES];         // [b][t][n], pre-augmented
__device__ float    g_S[2 * BB * NRES];          // double-buffered state
__device__ unsigned g_barCnt = 0;
__device__ unsigned g_barGen = 0;

// ---------------- software grid barrier (proven atomic version) --------------
__device__ __forceinline__ void grid_sync(unsigned nblk) {
    __threadfence();
    __syncthreads();
    if (threadIdx.x == 0) {
        volatile unsigned* genp = &g_barGen;
        unsigned gen = *genp;
        if (atomicInc(&g_barCnt, nblk - 1) == nblk - 1) {
            *genp = gen + 1;
        } else {
            while (*genp == gen) { __nanosleep(64); }
        }
    }
    __syncthreads();
}

// ---------------- Wres -> WresT (padded) -------------------------------------
__global__ void k_transpose(const float* __restrict__ Wres) {
    __shared__ float tile[32][33];
    int tx = threadIdx.x, ty = threadIdx.y;
    int k0 = blockIdx.x * 32;           // k tile (0..2047)
    int n0 = blockIdx.y * 32;           // n tile (0..1999)
    int k = k0 + ty, n = n0 + tx;
    float v = 0.f;
    if (k < NRES && n < NRES) v = Wres[k * NRES + n];
    tile[ty][tx] = v;
    __syncthreads();
    int nn = n0 + ty, kk = k0 + tx;
    if (nn < NRES) g_WresT[nn * KPAD + kk] = tile[tx][ty];
}

// ---------------- U[t][b][n] = sum_d x[b][t][d] * Win[d][n] ------------------
__global__ void k_u(const float* __restrict__ x, const float* __restrict__ Win) {
    __shared__ float xs[BB][DD];
    int t = blockIdx.x, tid = threadIdx.x;
    if (tid < BB * (DD / 4)) {
        int b = tid / (DD / 4), q = tid % (DD / 4);
        ((float4*)&xs[b][0])[q] = ((const float4*)(x + (size_t)(b * TT + t) * DD))[q];
    }
    __syncthreads();
    for (int n = tid; n < NRES; n += blockDim.x) {
        float acc[BB];
        #pragma unroll
        for (int b = 0; b < BB; b++) acc[b] = 0.f;
        #pragma unroll
        for (int d4 = 0; d4 < DD / 4; d4++) {
            float w0 = Win[(d4 * 4 + 0) * NRES + n];
            float w1 = Win[(d4 * 4 + 1) * NRES + n];
            float w2 = Win[(d4 * 4 + 2) * NRES + n];
            float w3 = Win[(d4 * 4 + 3) * NRES + n];
            #pragma unroll
            for (int b = 0; b < BB; b++) {
                float4 xv = *(const float4*)&xs[b][d4 * 4];
                acc[b] = fmaf(xv.x, w0, acc[b]);
                acc[b] = fmaf(xv.y, w1, acc[b]);
                acc[b] = fmaf(xv.z, w2, acc[b]);
                acc[b] = fmaf(xv.w, w3, acc[b]);
            }
        }
        #pragma unroll
        for (int b = 0; b < BB; b++) g_U[(size_t)(t * BB + b) * NRES + n] = acc[b];
    }
}

// ---------------- persistent recurrence kernel (R1 layout) -------------------
// warp = (kh, cs): 4 cols x 8 b register tile over a 1024-float K-half.
// Reduction: 2 shuffle levels (xor 16, 8) -> lanes 0..7 hold 4-lane partials,
// stored to p_sh[2][8][132]; finalize sums 16 partials. (Was 5 levels.)
__global__ void __launch_bounds__(256, 1) k_esn() {
    extern __shared__ float smem[];
    float* s_sh = smem;                 // BB * KPAD
    float* w_sh = smem + BB * KPAD;     // MAXC * KPAD
    __shared__ float p_sh[2][8][132];   // [kh][lane-slot][col*8+b], stride 132

    const int tid  = threadIdx.x;
    const int lane = tid & 31;
    const int warp = tid >> 5;
    const int nblk = gridDim.x;
    const int bid  = blockIdx.x;

    const int base = NRES / nblk, rem = NRES % nblk;
    const int c0    = bid * base + (bid < rem ? bid : rem);
    const int ncols = base + (bid < rem ? 1 : 0);   // <= 16

    // preload this block's WresT slice into smem (once)
    {
        float4*       w4  = (float4*)w_sh;
        const float4* gW4 = (const float4*)g_WresT;
        for (int i = tid; i < MAXC * KQ; i += blockDim.x) {
            int c = i >> 9;
            int q = i & (KQ - 1);
            float4 v = make_float4(0.f, 0.f, 0.f, 0.f);
            if (c < ncols) v = gW4[(size_t)(c0 + c) * KQ + q];
            w4[i] = v;
        }
    }

    // zero state buffer 0 (grid-strided)
    for (int i = bid * blockDim.x + tid; i < BB * NRES; i += nblk * blockDim.x)
        g_S[i] = 0.f;

    grid_sync(nblk);

    const int kh = warp >> 2;           // K-half: 0 or 1
    const int cs = warp & 3;            // column-slot group: 4 cols each

    const int  f_slot = tid >> 3;       // finalize: tid < 128
    const int  f_b    = tid & 7;
    const bool f_act  = (tid < MAXC * BB) && (f_slot < ncols);
    const int  f_col  = c0 + f_slot;

    const float4* wr0 = (const float4*)w_sh + (size_t)(cs * 4 + 0) * KQ;
    const float4* wr1 = (const float4*)w_sh + (size_t)(cs * 4 + 1) * KQ;
    const float4* wr2 = (const float4*)w_sh + (size_t)(cs * 4 + 2) * KQ;
    const float4* wr3 = (const float4*)w_sh + (size_t)(cs * 4 + 3) * KQ;
    const float4* sB  = (const float4*)s_sh;

    #pragma unroll 1
    for (int t = 0; t < TT; t++) {
        const int buf = t & 1;

        // prefetch this step's input-projection value
        float uval = 0.f;
        if (f_act) uval = __ldg(&g_U[(size_t)(t * BB + f_b) * NRES + f_col]);

        // stage S (L2) -> smem, zero-padded to 2048
        {
            const float* Sp = g_S + (size_t)buf * (BB * NRES);
            float4* s4 = (float4*)s_sh;
            for (int i = tid; i < BB * KQ; i += blockDim.x) {
                int b = i >> 9;
                int q = i & (KQ - 1);
                float4 v = make_float4(0.f, 0.f, 0.f, 0.f);
                if (q * 4 < NRES)
                    v = __ldcg((const float4*)(Sp + (size_t)b * NRES + q * 4));
                s4[(size_t)b * KQ + q] = v;
            }
        }
        __syncthreads();

        // 4 cols x 8 batch rows per warp, over this warp's K-half
        float acc[4][8];
        #pragma unroll
        for (int c = 0; c < 4; c++)
            #pragma unroll
            for (int b = 0; b < 8; b++) acc[c][b] = 0.f;

        #pragma unroll
        for (int it = 0; it < 8; it++) {
            const int kq = kh * 256 + it * 32 + lane;
            const float4 w0 = wr0[kq];
            const float4 w1 = wr1[kq];
            const float4 w2 = wr2[kq];
            const float4 w3 = wr3[kq];
            #pragma unroll
            for (int b = 0; b < 8; b++) {
                const float4 s = sB[(size_t)b * KQ + kq];
                acc[0][b] = fmaf(s.x, w0.x, acc[0][b]);
                acc[0][b] = fmaf(s.y, w0.y, acc[0][b]);
                acc[0][b] = fmaf(s.z, w0.z, acc[0][b]);
                acc[0][b] = fmaf(s.w, w0.w, acc[0][b]);
                acc[1][b] = fmaf(s.x, w1.x, acc[1][b]);
                acc[1][b] = fmaf(s.y, w1.y, acc[1][b]);
                acc[1][b] = fmaf(s.z, w1.z, acc[1][b]);
                acc[1][b] = fmaf(s.w, w1.w, acc[1][b]);
                acc[2][b] = fmaf(s.x, w2.x, acc[2][b]);
                acc[2][b] = fmaf(s.y, w2.y, acc[2][b]);
                acc[2][b] = fmaf(s.z, w2.z, acc[2][b]);
                acc[2][b] = fmaf(s.w, w2.w, acc[2][b]);
                acc[3][b] = fmaf(s.x, w3.x, acc[3][b]);
                acc[3][b] = fmaf(s.y, w3.y, acc[3][b]);
                acc[3][b] = fmaf(s.z, w3.z, acc[3][b]);
                acc[3][b] = fmaf(s.w, w3.w, acc[3][b]);
            }
        }

        // 2-level reduction: lanes {l, l^8, l^16, l^24} merged
        #pragma unroll
        for (int c = 0; c < 4; c++)
            #pragma unroll
            for (int b = 0; b < 8; b++) {
                float v = acc[c][b];
                v += __shfl_xor_sync(0xFFFFFFFFu, v, 16);
                v += __shfl_xor_sync(0xFFFFFFFFu, v, 8);
                acc[c][b] = v;
            }
        if (lane < 8) {
            #pragma unroll
            for (int c = 0; c < 4; c++)
                #pragma unroll
                for (int b = 0; b < 8; b++)
                    p_sh[kh][lane][(cs * 4 + c) * 8 + b] = acc[c][b];
        }
        __syncthreads();

        if (f_act) {
            const int idx = f_slot * 8 + f_b;
            float v = uval;
            #pragma unroll
            for (int s = 0; s < 8; s++)
                v += p_sh[0][s][idx] + p_sh[1][s][idx];
            float h = tanhf(v);
            const int nbuf = buf ^ 1;
            __stcg(&g_S[(size_t)nbuf * (BB * NRES) + (size_t)f_b * NRES + f_col], h);
            float ha = ((f_col & 1) == 0) ? h * h : h;   // pre-augment for k_out
            g_H[((size_t)f_b * TT + t) * NRES + f_col] = ha;
        }

        grid_sync(nblk);
    }
}

// ---------------- readout: out[b][t][d] = Haug[b][t][:] @ Wout ---------------
#define OT   8
#define HSTR 2004
__global__ void __launch_bounds__(256, 2) k_out(const float* __restrict__ Wout,
                                                float* __restrict__ out) {
    extern __shared__ float hs[];            // [OT][HSTR]
    __shared__ float ps[4][64][OT];
    const int tid = threadIdx.x;
    const int b   = blockIdx.y;
    const int t0  = blockIdx.x * OT;

    for (int r = 0; r < OT; r++) {
        const float4* src = (const float4*)(g_H + ((size_t)b * TT + (t0 + r)) * NRES);
        float4*       dst = (float4*)(hs + r * HSTR);
        for (int i = tid; i < 500; i += 256) dst[i] = __ldcg(src + i);
    }
    __syncthreads();

    const int d  = tid & 63;
    const int nq = tid >> 6;                 // 0..3
    float acc[OT];
    #pragma unroll
    for (int r = 0; r < OT; r++) acc[r] = 0.f;

    for (int q = nq; q < 500; q += 4) {
        const int n = q * 4;
        const float w0 = __ldg(&Wout[(size_t)(n + 0) * DD + d]);
        const float w1 = __ldg(&Wout[(size_t)(n + 1) * DD + d]);
        const float w2 = __ldg(&Wout[(size_t)(n + 2) * DD + d]);
        const float w3 = __ldg(&Wout[(size_t)(n + 3) * DD + d]);
        #pragma unroll
        for (int r = 0; r < OT; r++) {
            const float4 h4 = *(const float4*)(hs + r * HSTR + n);
            acc[r] = fmaf(h4.x, w0, acc[r]);
            acc[r] = fmaf(h4.y, w1, acc[r]);
            acc[r] = fmaf(h4.z, w2, acc[r]);
            acc[r] = fmaf(h4.w, w3, acc[r]);
        }
    }
    #pragma unroll
    for (int r = 0; r < OT; r++) ps[nq][d][r] = acc[r];
    __syncthreads();

    for (int i = tid; i < 64 * OT; i += 256) {
        int dd = i >> 3, rr = i & (OT - 1);
        float v = ps[0][dd][rr] + ps[1][dd][rr] + ps[2][dd][rr] + ps[3][dd][rr];
        out[((size_t)b * TT + (t0 + rr)) * DD + dd] = v;
    }
}

// ---------------- launch ------------------------------------------------------
extern "C" void kernel_launch(void* const* d_in, const int* in_sizes, int n_in,
                              void* d_out, int out_size) {
    const float* x    = (const float*)d_in[0];
    const float* Win  = (const float*)d_in[1];
    const float* Wres = (const float*)d_in[2];
    const float* Wout = (const float*)d_in[3];
    float*       out  = (float*)d_out;

    int dev = 0;
    cudaGetDevice(&dev);
    int nsm = 148;
    cudaDeviceGetAttribute(&nsm, cudaDevAttrMultiProcessorCount, dev);
    int nblk = nsm < 148 ? nsm : 148;   // 1 block/SM, all resident
    if (nblk < 125) nblk = 125;         // 16-slot capacity guard

    const size_t smem_main = (size_t)(BB * KPAD + MAXC * KPAD) * sizeof(float); // 192 KB
    cudaFuncSetAttribute(k_esn, cudaFuncAttributeMaxDynamicSharedMemorySize, (int)smem_main);
    const size_t smem_out = (size_t)OT * HSTR * sizeof(float);                  // ~64 KB
    cudaFuncSetAttribute(k_out, cudaFuncAttributeMaxDynamicSharedMemorySize, (int)smem_out);

    k_transpose<<<dim3(KPAD / 32, (NRES + 31) / 32), dim3(32, 32)>>>(Wres);
    k_u<<<TT, 256>>>(x, Win);
    k_esn<<<nblk, 256, smem_main>>>();
    k_out<<<dim3(TT / OT, BB), 256, smem_out>>>(Wout, out);
}